// round 4
// baseline (speedup 1.0000x reference)
#include <cuda_runtime.h>
#include <math.h>

#define HID 128
#define MAXN 100352
#define MAXE 1664000

// ---------------- scratch (device globals: no allocation allowed) ----------------
__device__ __align__(16) float g_X1 [(size_t)MAXN * HID];  // event_feat = relu(ev@Wp+bp)
__device__ __align__(16) float g_X  [(size_t)MAXN * HID];  // event_feat @ W_gcn (pre-norm)
__device__ __align__(16) float g_AGG[(size_t)MAXN * HID];  // normalized scatter-sum
__device__ __align__(16) float g_C  [(size_t)MAXN * HID];  // corrected
__device__ float g_dis[MAXN];
__device__ int   g_cnt[MAXN];      // in-degree (edges only)
__device__ int   g_off[MAXN];      // CSR offsets (exclusive scan)
__device__ int   g_cur[MAXN];      // fill cursors
__device__ int   g_bsum[128];      // scan partials
__device__ int   g_bsum_ex[128];
__device__ int   g_esrc[MAXE];     // CSR: src node per incoming edge

// ---------------- f32x2 packed-FMA helpers ----------------
__device__ __forceinline__ unsigned long long pk2(float lo, float hi) {
    unsigned long long r;
    asm("mov.b64 %0, {%1,%2};" : "=l"(r) : "f"(lo), "f"(hi));
    return r;
}
__device__ __forceinline__ unsigned long long bc2(float x) { return pk2(x, x); }
__device__ __forceinline__ void up2(unsigned long long v, float& lo, float& hi) {
    asm("mov.b64 {%0,%1}, %2;" : "=f"(lo), "=f"(hi) : "l"(v));
}
__device__ __forceinline__ unsigned long long ffma2(unsigned long long a,
                                                    unsigned long long b,
                                                    unsigned long long c) {
    unsigned long long d;
    asm("fma.rn.f32x2 %0, %1, %2, %3;" : "=l"(d) : "l"(a), "l"(b), "l"(c));
    return d;
}

enum Mode { M_PROJ = 0, M_GCN = 1, M_GATE = 2, M_FUSE = 3 };

// ---------------- fused GEMM: out[N,128] = f(A[N,K] @ W[K,128]) ----------------
// 256 threads: 4 row-groups x 64 column-pairs. Each thread: ROWS/4 rows x 2 cols.
template <int K, int ROWS, int MODE>
__global__ void __launch_bounds__(256) gemm_kernel(
    const float* __restrict__ A,     // PROJ: event_vector; GATE/FUSE: base_feat
    const float* __restrict__ W,
    const float* __restrict__ bias,  // b_proj / unused / b_gate / b_fuse
    const float* __restrict__ bgcn,  // b_gcn (GATE tile-load transform)
    float* __restrict__ outp,        // FUSE: d_out
    int N)
{
    __shared__ __align__(16) float xs[ROWS * K];
    const int tid  = threadIdx.x;
    const int grp  = tid >> 6;   // 0..3
    const int c    = tid & 63;   // column pair -> cols 2c, 2c+1
    const int row0 = blockIdx.x * ROWS;
    constexpr int RPT = ROWS / 4;

    // ---- stage A tile (with per-mode transform) ----
    const int nf4 = ROWS * (K / 4);
    for (int f = tid; f < nf4; f += 256) {
        int r  = f / (K / 4);
        int kk = (f % (K / 4)) * 4;
        int row = row0 + r;
        float4 v = make_float4(0.f, 0.f, 0.f, 0.f);
        if (row < N) {
            if (MODE == M_GATE || MODE == M_FUSE) {
                if (kk < HID) {
                    v = *(const float4*)(A + (size_t)row * HID + kk);
                } else {
                    int j = kk - HID;
                    if (MODE == M_GATE) {
                        float4 a = *(const float4*)(&g_AGG[(size_t)row * HID + j]);
                        float4 b = *(const float4*)(bgcn + j);
                        v.x = fmaxf(a.x + b.x, 0.f);
                        v.y = fmaxf(a.y + b.y, 0.f);
                        v.z = fmaxf(a.z + b.z, 0.f);
                        v.w = fmaxf(a.w + b.w, 0.f);
                    } else {
                        v = *(const float4*)(&g_C[(size_t)row * HID + j]);
                    }
                }
            } else if (MODE == M_GCN) {
                v = *(const float4*)(&g_X1[(size_t)row * K + kk]);
            } else {  // PROJ
                v = *(const float4*)(A + (size_t)row * K + kk);
            }
        }
        *(float4*)(&xs[r * K + kk]) = v;
    }
    __syncthreads();

    // ---- main loop ----
    unsigned long long acc[RPT];
#pragma unroll
    for (int r = 0; r < RPT; r++) acc[r] = 0ull;  // bits of (0.f,0.f)

    const float2* W2 = (const float2*)W;
    const float* xbase = &xs[grp * RPT * K];

    for (int k = 0; k < K; k += 4) {
        float2 w0 = W2[(k + 0) * 64 + c];
        float2 w1 = W2[(k + 1) * 64 + c];
        float2 w2 = W2[(k + 2) * 64 + c];
        float2 w3 = W2[(k + 3) * 64 + c];
        unsigned long long pw0 = pk2(w0.x, w0.y);
        unsigned long long pw1 = pk2(w1.x, w1.y);
        unsigned long long pw2 = pk2(w2.x, w2.y);
        unsigned long long pw3 = pk2(w3.x, w3.y);
#pragma unroll
        for (int r = 0; r < RPT; r++) {
            float4 xv = *(const float4*)(xbase + r * K + k);
            acc[r] = ffma2(bc2(xv.x), pw0, acc[r]);
            acc[r] = ffma2(bc2(xv.y), pw1, acc[r]);
            acc[r] = ffma2(bc2(xv.z), pw2, acc[r]);
            acc[r] = ffma2(bc2(xv.w), pw3, acc[r]);
        }
    }

    // ---- epilogue ----
    float2 bb = make_float2(0.f, 0.f);
    if (MODE != M_GCN) bb = ((const float2*)bias)[c];

#pragma unroll
    for (int r = 0; r < RPT; r++) {
        int row = row0 + grp * RPT + r;
        if (row >= N) break;
        float vx, vy;
        up2(acc[r], vx, vy);
        if (MODE == M_PROJ) {
            vx = fmaxf(vx + bb.x, 0.f);
            vy = fmaxf(vy + bb.y, 0.f);
            ((float2*)(&g_X1[(size_t)row * HID]))[c] = make_float2(vx, vy);
        } else if (MODE == M_GCN) {
            ((float2*)(&g_X[(size_t)row * HID]))[c] = make_float2(vx, vy);
        } else if (MODE == M_GATE) {
            float gx = 1.f / (1.f + expf(-(vx + bb.x)));
            float gy = 1.f / (1.f + expf(-(vy + bb.y)));
            const float* xr = xbase + r * K;
            float2 bv = *(const float2*)(xr + 2 * c);        // base
            float2 dv = *(const float2*)(xr + HID + 2 * c);  // diffused (relu'd)
            float cx = bv.x * (1.f - gx) + dv.x * gx;
            float cy = bv.y * (1.f - gy) + dv.y * gy;
            ((float2*)(&g_C[(size_t)row * HID]))[c] = make_float2(cx, cy);
        } else {  // FUSE
            vx = fmaxf(vx + bb.x, 0.f);
            vy = fmaxf(vy + bb.y, 0.f);
            ((float2*)(outp + (size_t)row * HID))[c] = make_float2(vx, vy);
        }
    }
}

// ---------------- CSR build (edge_index delivered as int32) ----------------
__global__ void zero_cnt(int N) {
    int i = blockIdx.x * blockDim.x + threadIdx.x;
    if (i < N) g_cnt[i] = 0;
}

__global__ void hist(const int* __restrict__ dst, int E, int N) {
    for (int e = blockIdx.x * blockDim.x + threadIdx.x; e < E;
         e += gridDim.x * blockDim.x) {
        unsigned d = (unsigned)dst[e];
        if (d < (unsigned)N) atomicAdd(&g_cnt[d], 1);
    }
}

// per-block inclusive scan of g_cnt -> exclusive offsets (block-local) + partials
__global__ void scan1(int N) {
    __shared__ int sm[1024];
    int i = blockIdx.x * 1024 + threadIdx.x;
    int v = (i < N) ? g_cnt[i] : 0;
    sm[threadIdx.x] = v;
    __syncthreads();
#pragma unroll
    for (int ofs = 1; ofs < 1024; ofs <<= 1) {
        int t = (threadIdx.x >= ofs) ? sm[threadIdx.x - ofs] : 0;
        __syncthreads();
        sm[threadIdx.x] += t;
        __syncthreads();
    }
    if (i < N) g_off[i] = sm[threadIdx.x] - v;   // block-local exclusive
    if (threadIdx.x == 1023) g_bsum[blockIdx.x] = sm[1023];
}

__global__ void scan2(int nb) {  // single block, nb <= 128
    __shared__ int sm[128];
    int v = (threadIdx.x < nb) ? g_bsum[threadIdx.x] : 0;
    sm[threadIdx.x] = v;
    __syncthreads();
#pragma unroll
    for (int ofs = 1; ofs < 128; ofs <<= 1) {
        int t = (threadIdx.x >= ofs) ? sm[threadIdx.x - ofs] : 0;
        __syncthreads();
        sm[threadIdx.x] += t;
        __syncthreads();
    }
    if (threadIdx.x < nb) g_bsum_ex[threadIdx.x] = sm[threadIdx.x] - v;
}

__global__ void scan3(int N) {  // add block offsets; init cursors; dis = rsqrt(deg)
    int i = blockIdx.x * 1024 + threadIdx.x;
    if (i >= N) return;
    int o = g_off[i] + g_bsum_ex[blockIdx.x];
    g_off[i] = o;
    g_cur[i] = o;
    g_dis[i] = rsqrtf((float)(g_cnt[i] + 1));  // +1 self-loop
}

__global__ void fill_csr(const int* __restrict__ src,
                         const int* __restrict__ dst, int E, int N) {
    for (int e = blockIdx.x * blockDim.x + threadIdx.x; e < E;
         e += gridDim.x * blockDim.x) {
        unsigned d = (unsigned)dst[e];
        unsigned s = (unsigned)src[e];
        if (d < (unsigned)N && s < (unsigned)N) {
            int pos = atomicAdd(&g_cur[d], 1);
            if (pos < MAXE) g_esrc[pos] = (int)s;
        }
    }
}

// ---------------- aggregation: one warp per node, register accumulation ----------------
__global__ void __launch_bounds__(256) aggregate(int N) {
    int warp = (blockIdx.x * blockDim.x + threadIdx.x) >> 5;
    int lane = threadIdx.x & 31;
    if (warp >= N) return;
    int node = warp;
    float dd = g_dis[node];
    float inv = dd * dd;  // self-loop norm

    float4 acc = *(const float4*)(&g_X[(size_t)node * HID + lane * 4]);
    acc.x *= inv; acc.y *= inv; acc.z *= inv; acc.w *= inv;

    int beg = g_off[node];
    int end = beg + g_cnt[node];
    for (int i = beg; i < end; i++) {
        int s = g_esrc[i];                 // broadcast load
        float nrm = g_dis[s] * dd;         // broadcast load
        float4 v = *(const float4*)(&g_X[(size_t)s * HID + lane * 4]);
        acc.x = fmaf(v.x, nrm, acc.x);
        acc.y = fmaf(v.y, nrm, acc.y);
        acc.z = fmaf(v.z, nrm, acc.z);
        acc.w = fmaf(v.w, nrm, acc.w);
    }
    *(float4*)(&g_AGG[(size_t)node * HID + lane * 4]) = acc;
}

// ---------------- launch ----------------
extern "C" void kernel_launch(void* const* d_in, const int* in_sizes, int n_in,
                              void* d_out, int out_size) {
    const float* base = (const float*)d_in[0];
    const float* ev   = (const float*)d_in[1];
    const int*   ei   = (const int*)d_in[2];   // int64 in ref -> int32 in harness
    const float* Wp = (const float*)d_in[3];
    const float* bp = (const float*)d_in[4];
    const float* Wg = (const float*)d_in[5];
    const float* bg = (const float*)d_in[6];
    const float* Wga = (const float*)d_in[7];
    const float* bga = (const float*)d_in[8];
    const float* Wf = (const float*)d_in[9];
    const float* bf = (const float*)d_in[10];
    float* out = (float*)d_out;

    const int N = in_sizes[0] / HID;
    const int E = in_sizes[2] / 2;
    const int* src = ei;
    const int* dst = ei + E;
    const int nb = (N + 1023) / 1024;

    // 1. event_feat = relu(ev @ W_proj + b_proj)
    gemm_kernel<64, 64, M_PROJ><<<(N + 63) / 64, 256>>>(ev, Wp, bp, nullptr, nullptr, N);
    // 2. x = event_feat @ W_gcn
    gemm_kernel<128, 64, M_GCN><<<(N + 63) / 64, 256>>>(nullptr, Wg, nullptr, nullptr, nullptr, N);
    // 3. CSR build
    zero_cnt<<<(N + 255) / 256, 256>>>(N);
    hist<<<2368, 256>>>(dst, E, N);
    scan1<<<nb, 1024>>>(N);
    scan2<<<1, 128>>>(nb);
    scan3<<<nb, 1024>>>(N);
    fill_csr<<<2368, 256>>>(src, dst, E, N);
    // 4. gather-aggregate (no float atomics)
    aggregate<<<(N * 32 + 255) / 256, 256>>>(N);
    // 5. gate + corrected (diffused = relu(agg + b_gcn) computed at tile load)
    gemm_kernel<256, 44, M_GATE><<<(N + 43) / 44, 256>>>(base, Wga, bga, bg, nullptr, N);
    // 6. out = relu([base, corrected] @ W_fuse + b_fuse)
    gemm_kernel<256, 44, M_FUSE><<<(N + 43) / 44, 256>>>(base, Wf, bf, nullptr, out, N);
}

// round 8
// speedup vs baseline: 1.0513x; 1.0513x over previous
#include <cuda_runtime.h>
#include <math.h>

#define HID 128
#define MAXN 100352
#define MAXE 1664000

// ---------------- scratch (device globals: no allocation allowed) ----------------
__device__ __align__(16) float g_X  [(size_t)MAXN * HID];  // event_feat @ W_gcn (pre-norm)
__device__ __align__(16) float g_AGG[(size_t)MAXN * HID];  // normalized scatter-sum
__device__ float g_dis[MAXN];
__device__ int   g_cnt[MAXN];      // in-degree (edges only)
__device__ int   g_off[MAXN];      // CSR offsets (exclusive scan)
__device__ int   g_cur[MAXN];      // fill cursors
__device__ int   g_bsum[128];      // scan partials
__device__ int   g_bsum_ex[128];
__device__ int   g_esrc[MAXE];     // CSR: src node per incoming edge

// ---------------- f32x2 packed-FMA helpers ----------------
__device__ __forceinline__ unsigned long long pk2(float lo, float hi) {
    unsigned long long r;
    asm("mov.b64 %0, {%1,%2};" : "=l"(r) : "f"(lo), "f"(hi));
    return r;
}
__device__ __forceinline__ unsigned long long bc2(float x) { return pk2(x, x); }
__device__ __forceinline__ void up2(unsigned long long v, float& lo, float& hi) {
    asm("mov.b64 {%0,%1}, %2;" : "=f"(lo), "=f"(hi) : "l"(v));
}
__device__ __forceinline__ unsigned long long ffma2(unsigned long long a,
                                                    unsigned long long b,
                                                    unsigned long long c) {
    unsigned long long d;
    asm("fma.rn.f32x2 %0, %1, %2, %3;" : "=l"(d) : "l"(a), "l"(b), "l"(c));
    return d;
}

// ================= Fused PROJ + GCN =================
// E1 = relu(ev @ Wp + bp) kept in smem; X = E1 @ Wg written to g_X.
// 256 threads: 4 row-groups x 64 col-pairs; ROWS=64, RPT=16.
__global__ void __launch_bounds__(256) proj_gcn_kernel(
    const float* __restrict__ ev, const float* __restrict__ Wp,
    const float* __restrict__ bp, const float* __restrict__ Wg, int N)
{
    __shared__ __align__(16) float ev_s[64 * 64];    // 16 KB
    __shared__ __align__(16) float e1_s[64 * 128];   // 32 KB
    const int tid  = threadIdx.x;
    const int grp  = tid >> 6;
    const int c    = tid & 63;
    const int row0 = blockIdx.x * 64;

    // stage event tile
    for (int f = tid; f < 64 * 16; f += 256) {
        int r  = f >> 4;
        int kk = (f & 15) * 4;
        int row = row0 + r;
        float4 v = make_float4(0.f, 0.f, 0.f, 0.f);
        if (row < N) v = *(const float4*)(ev + (size_t)row * 64 + kk);
        *(float4*)(&ev_s[r * 64 + kk]) = v;
    }
    __syncthreads();

    // phase 1: E1 = relu(ev @ Wp + bp), K=64
    {
        unsigned long long acc[16];
#pragma unroll
        for (int r = 0; r < 16; r++) acc[r] = 0ull;
        const float2* W2 = (const float2*)Wp;
        const float* xbase = &ev_s[grp * 16 * 64];
        for (int k = 0; k < 64; k += 4) {
            float2 w0 = W2[(k + 0) * 64 + c];
            float2 w1 = W2[(k + 1) * 64 + c];
            float2 w2 = W2[(k + 2) * 64 + c];
            float2 w3 = W2[(k + 3) * 64 + c];
            unsigned long long pw0 = pk2(w0.x, w0.y);
            unsigned long long pw1 = pk2(w1.x, w1.y);
            unsigned long long pw2 = pk2(w2.x, w2.y);
            unsigned long long pw3 = pk2(w3.x, w3.y);
#pragma unroll
            for (int r = 0; r < 16; r++) {
                float4 xv = *(const float4*)(xbase + r * 64 + k);
                acc[r] = ffma2(bc2(xv.x), pw0, acc[r]);
                acc[r] = ffma2(bc2(xv.y), pw1, acc[r]);
                acc[r] = ffma2(bc2(xv.z), pw2, acc[r]);
                acc[r] = ffma2(bc2(xv.w), pw3, acc[r]);
            }
        }
        float2 bb = ((const float2*)bp)[c];
#pragma unroll
        for (int r = 0; r < 16; r++) {
            float vx, vy;
            up2(acc[r], vx, vy);
            vx = fmaxf(vx + bb.x, 0.f);
            vy = fmaxf(vy + bb.y, 0.f);
            ((float2*)(&e1_s[(grp * 16 + r) * HID]))[c] = make_float2(vx, vy);
        }
    }
    __syncthreads();

    // phase 2: X = E1 @ Wg, K=128, no bias (added later)
    {
        unsigned long long acc[16];
#pragma unroll
        for (int r = 0; r < 16; r++) acc[r] = 0ull;
        const float2* W2 = (const float2*)Wg;
        const float* xbase = &e1_s[grp * 16 * HID];
        for (int k = 0; k < 128; k += 4) {
            float2 w0 = W2[(k + 0) * 64 + c];
            float2 w1 = W2[(k + 1) * 64 + c];
            float2 w2 = W2[(k + 2) * 64 + c];
            float2 w3 = W2[(k + 3) * 64 + c];
            unsigned long long pw0 = pk2(w0.x, w0.y);
            unsigned long long pw1 = pk2(w1.x, w1.y);
            unsigned long long pw2 = pk2(w2.x, w2.y);
            unsigned long long pw3 = pk2(w3.x, w3.y);
#pragma unroll
            for (int r = 0; r < 16; r++) {
                float4 xv = *(const float4*)(xbase + r * HID + k);
                acc[r] = ffma2(bc2(xv.x), pw0, acc[r]);
                acc[r] = ffma2(bc2(xv.y), pw1, acc[r]);
                acc[r] = ffma2(bc2(xv.z), pw2, acc[r]);
                acc[r] = ffma2(bc2(xv.w), pw3, acc[r]);
            }
        }
#pragma unroll
        for (int r = 0; r < 16; r++) {
            int row = row0 + grp * 16 + r;
            if (row >= N) break;
            float vx, vy;
            up2(acc[r], vx, vy);
            ((float2*)(&g_X[(size_t)row * HID]))[c] = make_float2(vx, vy);
        }
    }
}

// ================= Fused GATE + FUSE =================
// xs = [base | relu(agg + b_gcn)]; gate = sigmoid(xs @ Wga + bga);
// corrected replaces xs[:,128:]; out = relu(xs @ Wf + bf).
// ROWS=32, RPT=8, K=256.
__global__ void __launch_bounds__(256) gate_fuse_kernel(
    const float* __restrict__ base, const float* __restrict__ Wga,
    const float* __restrict__ bga,  const float* __restrict__ bgcn,
    const float* __restrict__ Wf,   const float* __restrict__ bf,
    float* __restrict__ outp, int N)
{
    __shared__ __align__(16) float xs[32 * 256];  // 32 KB
    const int tid  = threadIdx.x;
    const int grp  = tid >> 6;
    const int c    = tid & 63;
    const int row0 = blockIdx.x * 32;

    // stage [base | diffused]
    for (int f = tid; f < 32 * 64; f += 256) {
        int r  = f >> 6;
        int kk = (f & 63) * 4;
        int row = row0 + r;
        float4 v = make_float4(0.f, 0.f, 0.f, 0.f);
        if (row < N) {
            if (kk < HID) {
                v = *(const float4*)(base + (size_t)row * HID + kk);
            } else {
                int j = kk - HID;
                float4 a = *(const float4*)(&g_AGG[(size_t)row * HID + j]);
                float4 b = *(const float4*)(bgcn + j);
                v.x = fmaxf(a.x + b.x, 0.f);
                v.y = fmaxf(a.y + b.y, 0.f);
                v.z = fmaxf(a.z + b.z, 0.f);
                v.w = fmaxf(a.w + b.w, 0.f);
            }
        }
        *(float4*)(&xs[r * 256 + kk]) = v;
    }
    __syncthreads();

    unsigned long long acc[8];
    const float* xbase = &xs[grp * 8 * 256];

    // ---- GEMM 1: gate logits ----
#pragma unroll
    for (int r = 0; r < 8; r++) acc[r] = 0ull;
    {
        const float2* W2 = (const float2*)Wga;
        for (int k = 0; k < 256; k += 4) {
            float2 w0 = W2[(k + 0) * 64 + c];
            float2 w1 = W2[(k + 1) * 64 + c];
            float2 w2 = W2[(k + 2) * 64 + c];
            float2 w3 = W2[(k + 3) * 64 + c];
            unsigned long long pw0 = pk2(w0.x, w0.y);
            unsigned long long pw1 = pk2(w1.x, w1.y);
            unsigned long long pw2 = pk2(w2.x, w2.y);
            unsigned long long pw3 = pk2(w3.x, w3.y);
#pragma unroll
            for (int r = 0; r < 8; r++) {
                float4 xv = *(const float4*)(xbase + r * 256 + k);
                acc[r] = ffma2(bc2(xv.x), pw0, acc[r]);
                acc[r] = ffma2(bc2(xv.y), pw1, acc[r]);
                acc[r] = ffma2(bc2(xv.z), pw2, acc[r]);
                acc[r] = ffma2(bc2(xv.w), pw3, acc[r]);
            }
        }
    }
    // gate -> corrected (into registers; packed back into acc)
    {
        float2 bb = ((const float2*)bga)[c];
#pragma unroll
        for (int r = 0; r < 8; r++) {
            float vx, vy;
            up2(acc[r], vx, vy);
            float gx = 1.f / (1.f + expf(-(vx + bb.x)));
            float gy = 1.f / (1.f + expf(-(vy + bb.y)));
            const float* xr = xbase + r * 256;
            float2 bv = *(const float2*)(xr + 2 * c);        // base
            float2 dv = *(const float2*)(xr + HID + 2 * c);  // diffused
            float cx = bv.x * (1.f - gx) + dv.x * gx;
            float cy = bv.y * (1.f - gy) + dv.y * gy;
            acc[r] = pk2(cx, cy);
        }
    }
    __syncthreads();   // all reads of old tile done
#pragma unroll
    for (int r = 0; r < 8; r++) {
        float cx, cy;
        up2(acc[r], cx, cy);
        ((float2*)(&xs[(grp * 8 + r) * 256 + HID]))[c] = make_float2(cx, cy);
    }
    __syncthreads();   // corrected visible to the whole group

    // ---- GEMM 2: out = relu([base|corrected] @ Wf + bf) ----
#pragma unroll
    for (int r = 0; r < 8; r++) acc[r] = 0ull;
    {
        const float2* W2 = (const float2*)Wf;
        for (int k = 0; k < 256; k += 4) {
            float2 w0 = W2[(k + 0) * 64 + c];
            float2 w1 = W2[(k + 1) * 64 + c];
            float2 w2 = W2[(k + 2) * 64 + c];
            float2 w3 = W2[(k + 3) * 64 + c];
            unsigned long long pw0 = pk2(w0.x, w0.y);
            unsigned long long pw1 = pk2(w1.x, w1.y);
            unsigned long long pw2 = pk2(w2.x, w2.y);
            unsigned long long pw3 = pk2(w3.x, w3.y);
#pragma unroll
            for (int r = 0; r < 8; r++) {
                float4 xv = *(const float4*)(xbase + r * 256 + k);
                acc[r] = ffma2(bc2(xv.x), pw0, acc[r]);
                acc[r] = ffma2(bc2(xv.y), pw1, acc[r]);
                acc[r] = ffma2(bc2(xv.z), pw2, acc[r]);
                acc[r] = ffma2(bc2(xv.w), pw3, acc[r]);
            }
        }
    }
    {
        float2 bb = ((const float2*)bf)[c];
#pragma unroll
        for (int r = 0; r < 8; r++) {
            int row = row0 + grp * 8 + r;
            if (row >= N) break;
            float vx, vy;
            up2(acc[r], vx, vy);
            vx = fmaxf(vx + bb.x, 0.f);
            vy = fmaxf(vy + bb.y, 0.f);
            ((float2*)(outp + (size_t)row * HID))[c] = make_float2(vx, vy);
        }
    }
}

// ---------------- CSR build (edge_index delivered as int32) ----------------
__global__ void zero_cnt(int N) {
    int i = blockIdx.x * blockDim.x + threadIdx.x;
    if (i < N) g_cnt[i] = 0;
}

__global__ void hist(const int* __restrict__ dst, int E, int N) {
    for (int e = blockIdx.x * blockDim.x + threadIdx.x; e < E;
         e += gridDim.x * blockDim.x) {
        unsigned d = (unsigned)dst[e];
        if (d < (unsigned)N) atomicAdd(&g_cnt[d], 1);
    }
}

__global__ void scan1(int N) {
    __shared__ int sm[1024];
    int i = blockIdx.x * 1024 + threadIdx.x;
    int v = (i < N) ? g_cnt[i] : 0;
    sm[threadIdx.x] = v;
    __syncthreads();
#pragma unroll
    for (int ofs = 1; ofs < 1024; ofs <<= 1) {
        int t = (threadIdx.x >= ofs) ? sm[threadIdx.x - ofs] : 0;
        __syncthreads();
        sm[threadIdx.x] += t;
        __syncthreads();
    }
    if (i < N) g_off[i] = sm[threadIdx.x] - v;
    if (threadIdx.x == 1023) g_bsum[blockIdx.x] = sm[1023];
}

__global__ void scan2(int nb) {
    __shared__ int sm[128];
    int v = (threadIdx.x < nb) ? g_bsum[threadIdx.x] : 0;
    sm[threadIdx.x] = v;
    __syncthreads();
#pragma unroll
    for (int ofs = 1; ofs < 128; ofs <<= 1) {
        int t = (threadIdx.x >= ofs) ? sm[threadIdx.x - ofs] : 0;
        __syncthreads();
        sm[threadIdx.x] += t;
        __syncthreads();
    }
    if (threadIdx.x < nb) g_bsum_ex[threadIdx.x] = sm[threadIdx.x] - v;
}

__global__ void scan3(int N) {
    int i = blockIdx.x * 1024 + threadIdx.x;
    if (i >= N) return;
    int o = g_off[i] + g_bsum_ex[blockIdx.x];
    g_off[i] = o;
    g_cur[i] = o;
    g_dis[i] = rsqrtf((float)(g_cnt[i] + 1));  // +1 self-loop
}

__global__ void fill_csr(const int* __restrict__ src,
                         const int* __restrict__ dst, int E, int N) {
    for (int e = blockIdx.x * blockDim.x + threadIdx.x; e < E;
         e += gridDim.x * blockDim.x) {
        unsigned d = (unsigned)dst[e];
        unsigned s = (unsigned)src[e];
        if (d < (unsigned)N && s < (unsigned)N) {
            int pos = atomicAdd(&g_cur[d], 1);
            if (pos < MAXE) g_esrc[pos] = (int)s;
        }
    }
}

// ---------------- aggregation: one warp per node, register accumulation ----------------
__global__ void __launch_bounds__(256) aggregate(int N) {
    int warp = (blockIdx.x * blockDim.x + threadIdx.x) >> 5;
    int lane = threadIdx.x & 31;
    if (warp >= N) return;
    int node = warp;
    float dd = g_dis[node];
    float inv = dd * dd;  // self-loop norm

    float4 acc = *(const float4*)(&g_X[(size_t)node * HID + lane * 4]);
    acc.x *= inv; acc.y *= inv; acc.z *= inv; acc.w *= inv;

    int beg = g_off[node];
    int end = beg + g_cnt[node];
    int i = beg;
    for (; i + 2 <= end; i += 2) {
        int s0 = g_esrc[i];
        int s1 = g_esrc[i + 1];
        float n0 = g_dis[s0] * dd;
        float n1 = g_dis[s1] * dd;
        float4 v0 = *(const float4*)(&g_X[(size_t)s0 * HID + lane * 4]);
        float4 v1 = *(const float4*)(&g_X[(size_t)s1 * HID + lane * 4]);
        acc.x = fmaf(v0.x, n0, acc.x);
        acc.y = fmaf(v0.y, n0, acc.y);
        acc.z = fmaf(v0.z, n0, acc.z);
        acc.w = fmaf(v0.w, n0, acc.w);
        acc.x = fmaf(v1.x, n1, acc.x);
        acc.y = fmaf(v1.y, n1, acc.y);
        acc.z = fmaf(v1.z, n1, acc.z);
        acc.w = fmaf(v1.w, n1, acc.w);
    }
    if (i < end) {
        int s = g_esrc[i];
        float nrm = g_dis[s] * dd;
        float4 v = *(const float4*)(&g_X[(size_t)s * HID + lane * 4]);
        acc.x = fmaf(v.x, nrm, acc.x);
        acc.y = fmaf(v.y, nrm, acc.y);
        acc.z = fmaf(v.z, nrm, acc.z);
        acc.w = fmaf(v.w, nrm, acc.w);
    }
    *(float4*)(&g_AGG[(size_t)node * HID + lane * 4]) = acc;
}

// ---------------- launch ----------------
extern "C" void kernel_launch(void* const* d_in, const int* in_sizes, int n_in,
                              void* d_out, int out_size) {
    const float* base = (const float*)d_in[0];
    const float* ev   = (const float*)d_in[1];
    const int*   ei   = (const int*)d_in[2];   // int64 in ref -> int32 in harness
    const float* Wp = (const float*)d_in[3];
    const float* bp = (const float*)d_in[4];
    const float* Wg = (const float*)d_in[5];
    const float* bg = (const float*)d_in[6];
    const float* Wga = (const float*)d_in[7];
    const float* bga = (const float*)d_in[8];
    const float* Wf = (const float*)d_in[9];
    const float* bf = (const float*)d_in[10];
    float* out = (float*)d_out;

    const int N = in_sizes[0] / HID;
    const int E = in_sizes[2] / 2;
    const int* src = ei;
    const int* dst = ei + E;
    const int nb = (N + 1023) / 1024;

    // 1. X = (relu(ev @ Wp + bp)) @ Wg   [fused]
    proj_gcn_kernel<<<(N + 63) / 64, 256>>>(ev, Wp, bp, Wg, N);
    // 2. CSR build
    zero_cnt<<<(N + 255) / 256, 256>>>(N);
    hist<<<2368, 256>>>(dst, E, N);
    scan1<<<nb, 1024>>>(N);
    scan2<<<1, 128>>>(nb);
    scan3<<<nb, 1024>>>(N);
    fill_csr<<<2368, 256>>>(src, dst, E, N);
    // 3. gather-aggregate (no float atomics)
    aggregate<<<(N * 32 + 255) / 256, 256>>>(N);
    // 4. gate + corrected + fuse  [fused]
    gate_fuse_kernel<<<(N + 31) / 32, 256>>>(base, Wga, bga, bg, Wf, bf, out, N);
}

// round 11
// speedup vs baseline: 1.1132x; 1.0589x over previous
#include <cuda_runtime.h>
#include <cuda_bf16.h>
#include <stdint.h>
#include <math.h>

#define HID 128
#define MAXN 100352
#define MAXE 1664000

// ---------------- scratch (device globals: no allocation allowed) ----------------
__device__ __align__(16) float g_X  [(size_t)MAXN * HID];
__device__ __align__(16) float g_AGG[(size_t)MAXN * HID];
__device__ float g_dis[MAXN];
__device__ int   g_cnt[MAXN];
__device__ int   g_off[MAXN];
__device__ int   g_cur[MAXN];
__device__ int   g_bsum[128];
__device__ int   g_bsum_ex[128];
__device__ int   g_esrc[MAXE];
// bf16 hi/lo splits of W_gate and W_fuse, transposed to [N=128][K=256]
__device__ __align__(16) __nv_bfloat16 g_Wga_hi[128 * 256];
__device__ __align__(16) __nv_bfloat16 g_Wga_lo[128 * 256];
__device__ __align__(16) __nv_bfloat16 g_Wf_hi [128 * 256];
__device__ __align__(16) __nv_bfloat16 g_Wf_lo [128 * 256];

// ---------------- f32x2 packed-FMA helpers ----------------
__device__ __forceinline__ unsigned long long pk2(float lo, float hi) {
    unsigned long long r;
    asm("mov.b64 %0, {%1,%2};" : "=l"(r) : "f"(lo), "f"(hi));
    return r;
}
__device__ __forceinline__ unsigned long long bc2(float x) { return pk2(x, x); }
__device__ __forceinline__ void up2(unsigned long long v, float& lo, float& hi) {
    asm("mov.b64 {%0,%1}, %2;" : "=f"(lo), "=f"(hi) : "l"(v));
}
__device__ __forceinline__ unsigned long long ffma2(unsigned long long a,
                                                    unsigned long long b,
                                                    unsigned long long c) {
    unsigned long long d;
    asm("fma.rn.f32x2 %0, %1, %2, %3;" : "=l"(d) : "l"(a), "l"(b), "l"(c));
    return d;
}

// ---------------- mma helpers (baseline PTX, works on plain sm_103) ----------------
__device__ __forceinline__ uint32_t smem_u32(const void* p) {
    uint32_t a;
    asm("{.reg .u64 t; cvta.to.shared.u64 t, %1; cvt.u32.u64 %0, t;}" : "=r"(a) : "l"(p));
    return a;
}
__device__ __forceinline__ void ldm4(uint32_t* r, uint32_t addr) {
    asm volatile("ldmatrix.sync.aligned.m8n8.x4.shared.b16 {%0,%1,%2,%3}, [%4];"
                 : "=r"(r[0]), "=r"(r[1]), "=r"(r[2]), "=r"(r[3]) : "r"(addr));
}
__device__ __forceinline__ void mma_bf16(float* d, const uint32_t* a,
                                         uint32_t b0, uint32_t b1) {
    asm volatile(
        "mma.sync.aligned.m16n8k16.row.col.f32.bf16.bf16.f32 "
        "{%0,%1,%2,%3}, {%4,%5,%6,%7}, {%8,%9}, {%0,%1,%2,%3};"
        : "+f"(d[0]), "+f"(d[1]), "+f"(d[2]), "+f"(d[3])
        : "r"(a[0]), "r"(a[1]), "r"(a[2]), "r"(a[3]), "r"(b0), "r"(b1));
}
__device__ __forceinline__ uint32_t pkbf(float a, float b) {
    __nv_bfloat162 t = __floats2bfloat162_rn(a, b);
    return *(uint32_t*)&t;
}

// smem layout (bytes from dynamic base; base is 16B aligned)
// A: 128 rows x 256 cols bf16, row stride 264 elems (528B; 528 % 128 == 16 -> conflict-free ldmatrix)
// B: 128 rows(n) x 128 cols(k-half) bf16, row stride 136 elems (272B; 272 % 128 == 16)
#define SA 264
#define SB 136
#define A_HI 0u
#define A_LO 67584u
#define B_HI 135168u
#define B_LO 169984u
#define SMEM_BYTES 204800

// ================= W split prep (transpose to [n][k], bf16 hi/lo) =================
__global__ void prep_w(const float* __restrict__ Wga, const float* __restrict__ Wf) {
    int i = blockIdx.x * blockDim.x + threadIdx.x;  // over 256*128
    if (i >= 256 * 128) return;
    int k = i >> 7, n = i & 127;
    {
        float w = Wga[k * 128 + n];
        __nv_bfloat16 h = __float2bfloat16(w);
        g_Wga_hi[n * 256 + k] = h;
        g_Wga_lo[n * 256 + k] = __float2bfloat16(w - __bfloat162float(h));
    }
    {
        float w = Wf[k * 128 + n];
        __nv_bfloat16 h = __float2bfloat16(w);
        g_Wf_hi[n * 256 + k] = h;
        g_Wf_lo[n * 256 + k] = __float2bfloat16(w - __bfloat162float(h));
    }
}

// ================= HMMA GATE+FUSE =================
__global__ void __launch_bounds__(256, 1) gate_fuse_mma(
    const float* __restrict__ base, const float* __restrict__ bga,
    const float* __restrict__ bgcn, const float* __restrict__ bf,
    float* __restrict__ outp, int N)
{
    extern __shared__ char sm[];
    const uint32_t sb = smem_u32(sm);
    const int tid = threadIdx.x;
    const int wid = tid >> 5;
    const int lane = tid & 31;
    const int m0 = wid * 16;
    const int row0 = blockIdx.x * 128;

    // ---- stage A: [base | relu(AGG + bgcn)] as bf16 hi/lo ----
    for (int idx = tid; idx < 128 * 32; idx += 256) {
        int r = idx >> 5, c0 = (idx & 31) * 8;
        int row = row0 + r;
        float v[8];
        if (row < N) {
            if (c0 < 128) {
                float4 a = *(const float4*)(base + (size_t)row * HID + c0);
                float4 b = *(const float4*)(base + (size_t)row * HID + c0 + 4);
                v[0]=a.x; v[1]=a.y; v[2]=a.z; v[3]=a.w; v[4]=b.x; v[5]=b.y; v[6]=b.z; v[7]=b.w;
            } else {
                int j = c0 - 128;
                float4 a = *(const float4*)(&g_AGG[(size_t)row * HID + j]);
                float4 b = *(const float4*)(&g_AGG[(size_t)row * HID + j + 4]);
                float4 c = *(const float4*)(bgcn + j);
                float4 d = *(const float4*)(bgcn + j + 4);
                v[0]=fmaxf(a.x+c.x,0.f); v[1]=fmaxf(a.y+c.y,0.f);
                v[2]=fmaxf(a.z+c.z,0.f); v[3]=fmaxf(a.w+c.w,0.f);
                v[4]=fmaxf(b.x+d.x,0.f); v[5]=fmaxf(b.y+d.y,0.f);
                v[6]=fmaxf(b.z+d.z,0.f); v[7]=fmaxf(b.w+d.w,0.f);
            }
        } else {
            for (int t = 0; t < 8; t++) v[t] = 0.f;
        }
        uint32_t hi[4], lo[4];
#pragma unroll
        for (int t = 0; t < 4; t++) {
            float h0 = __bfloat162float(__float2bfloat16(v[2*t]));
            float h1 = __bfloat162float(__float2bfloat16(v[2*t+1]));
            hi[t] = pkbf(v[2*t], v[2*t+1]);
            lo[t] = pkbf(v[2*t] - h0, v[2*t+1] - h1);
        }
        uint32_t off = (uint32_t)r * (SA * 2) + c0 * 2;
        *(uint4*)(sm + A_HI + off) = make_uint4(hi[0], hi[1], hi[2], hi[3]);
        *(uint4*)(sm + A_LO + off) = make_uint4(lo[0], lo[1], lo[2], lo[3]);
    }

    // B staging: K-half kh of W (hi,lo) into B_HI/B_LO
    auto stageB = [&](const __nv_bfloat16* Wh, const __nv_bfloat16* Wl, int kh) {
        for (int idx = tid; idx < 128 * 16; idx += 256) {
            int n = idx >> 4, c0 = (idx & 15) * 8;
            uint32_t off = (uint32_t)n * (SB * 2) + c0 * 2;
            *(uint4*)(sm + B_HI + off) = *(const uint4*)(Wh + n * 256 + kh * 128 + c0);
            *(uint4*)(sm + B_LO + off) = *(const uint4*)(Wl + n * 256 + kh * 128 + c0);
        }
    };

    float d[16][4];
#pragma unroll
    for (int t = 0; t < 16; t++)
        for (int q = 0; q < 4; q++) d[t][q] = 0.f;

    // one K-half of a GEMM: ks = 0..7 local k-steps
    auto gemm_half = [&](int kh) {
        // B ldmatrix address pattern (covers 2 n-tiles per x4)
        int bn = (lane & 7) + ((lane >> 4) << 3);
        int bko = ((lane >> 3) & 1) << 3;
        // A ldmatrix address pattern
        int ar = m0 + (lane & 15);
        int ako = (lane >> 4) << 3;
#pragma unroll
        for (int ks = 0; ks < 8; ks++) {
            uint32_t ah[4], al[4];
            uint32_t aaddr = sb + A_HI + (uint32_t)ar * (SA * 2) + (kh * 128 + ks * 16 + ako) * 2;
            ldm4(ah, aaddr);
            ldm4(al, aaddr + (A_LO - A_HI));
#pragma unroll
            for (int np = 0; np < 8; np++) {
                uint32_t baddr = sb + B_HI + (uint32_t)(np * 16 + bn) * (SB * 2) + (ks * 16 + bko) * 2;
                uint32_t bh[4], bl[4];
                ldm4(bh, baddr);
                ldm4(bl, baddr + (B_LO - B_HI));
                mma_bf16(d[2*np],   ah, bh[0], bh[1]);
                mma_bf16(d[2*np],   al, bh[0], bh[1]);
                mma_bf16(d[2*np],   ah, bl[0], bl[1]);
                mma_bf16(d[2*np+1], ah, bh[2], bh[3]);
                mma_bf16(d[2*np+1], al, bh[2], bh[3]);
                mma_bf16(d[2*np+1], ah, bl[2], bl[3]);
            }
        }
    };

    // ---- GATE GEMM ----
    stageB(g_Wga_hi, g_Wga_lo, 0);
    __syncthreads();
    gemm_half(0);
    __syncthreads();
    stageB(g_Wga_hi, g_Wga_lo, 1);
    __syncthreads();
    gemm_half(1);
    __syncthreads();

    // ---- gate epilogue: sigmoid -> corrected -> re-split into A[:,128:256] ----
    {
        int ra = m0 + (lane >> 2);
        int ca = 2 * (lane & 3);
        int gra = row0 + ra;
        int grb = gra + 8;
#pragma unroll
        for (int nt = 0; nt < 16; nt++) {
            int n0 = nt * 8 + ca;
            float2 bb2 = *(const float2*)(bga + n0);
            float2 bg2 = *(const float2*)(bgcn + n0);
            // row ra (d[nt][0], d[nt][1])
            if (gra < N) {
                float2 bs = *(const float2*)(base + (size_t)gra * HID + n0);
                float2 ag = *(const float2*)(&g_AGG[(size_t)gra * HID + n0]);
                float dv0 = fmaxf(ag.x + bg2.x, 0.f), dv1 = fmaxf(ag.y + bg2.y, 0.f);
                float g0 = 1.f / (1.f + __expf(-(d[nt][0] + bb2.x)));
                float g1 = 1.f / (1.f + __expf(-(d[nt][1] + bb2.y)));
                float c0 = bs.x * (1.f - g0) + dv0 * g0;
                float c1 = bs.y * (1.f - g1) + dv1 * g1;
                float h0 = __bfloat162float(__float2bfloat16(c0));
                float h1 = __bfloat162float(__float2bfloat16(c1));
                uint32_t off = (uint32_t)ra * (SA * 2) + (128 + n0) * 2;
                *(uint32_t*)(sm + A_HI + off) = pkbf(c0, c1);
                *(uint32_t*)(sm + A_LO + off) = pkbf(c0 - h0, c1 - h1);
            }
            // row rb (d[nt][2], d[nt][3])
            if (grb < N) {
                float2 bs = *(const float2*)(base + (size_t)grb * HID + n0);
                float2 ag = *(const float2*)(&g_AGG[(size_t)grb * HID + n0]);
                float dv0 = fmaxf(ag.x + bg2.x, 0.f), dv1 = fmaxf(ag.y + bg2.y, 0.f);
                float g0 = 1.f / (1.f + __expf(-(d[nt][2] + bb2.x)));
                float g1 = 1.f / (1.f + __expf(-(d[nt][3] + bb2.y)));
                float c0 = bs.x * (1.f - g0) + dv0 * g0;
                float c1 = bs.y * (1.f - g1) + dv1 * g1;
                float h0 = __bfloat162float(__float2bfloat16(c0));
                float h1 = __bfloat162float(__float2bfloat16(c1));
                uint32_t off = (uint32_t)(ra + 8) * (SA * 2) + (128 + n0) * 2;
                *(uint32_t*)(sm + A_HI + off) = pkbf(c0, c1);
                *(uint32_t*)(sm + A_LO + off) = pkbf(c0 - h0, c1 - h1);
            }
            // reset accumulators for fuse GEMM
            d[nt][0] = d[nt][1] = d[nt][2] = d[nt][3] = 0.f;
        }
    }
    stageB(g_Wf_hi, g_Wf_lo, 0);
    __syncthreads();

    // ---- FUSE GEMM ----
    gemm_half(0);
    __syncthreads();
    stageB(g_Wf_hi, g_Wf_lo, 1);
    __syncthreads();
    gemm_half(1);

    // ---- fuse epilogue: relu(d + bf) -> out ----
    {
        int ra = m0 + (lane >> 2);
        int ca = 2 * (lane & 3);
        int gra = row0 + ra;
        int grb = gra + 8;
#pragma unroll
        for (int nt = 0; nt < 16; nt++) {
            int n0 = nt * 8 + ca;
            float2 bb2 = *(const float2*)(bf + n0);
            if (gra < N) {
                float2 o;
                o.x = fmaxf(d[nt][0] + bb2.x, 0.f);
                o.y = fmaxf(d[nt][1] + bb2.y, 0.f);
                *(float2*)(outp + (size_t)gra * HID + n0) = o;
            }
            if (grb < N) {
                float2 o;
                o.x = fmaxf(d[nt][2] + bb2.x, 0.f);
                o.y = fmaxf(d[nt][3] + bb2.y, 0.f);
                *(float2*)(outp + (size_t)grb * HID + n0) = o;
            }
        }
    }
}

// ================= Fused PROJ + GCN (ffma2, unchanged) =================
__global__ void __launch_bounds__(256) proj_gcn_kernel(
    const float* __restrict__ ev, const float* __restrict__ Wp,
    const float* __restrict__ bp, const float* __restrict__ Wg, int N)
{
    __shared__ __align__(16) float ev_s[64 * 64];
    __shared__ __align__(16) float e1_s[64 * 128];
    const int tid  = threadIdx.x;
    const int grp  = tid >> 6;
    const int c    = tid & 63;
    const int row0 = blockIdx.x * 64;

    for (int f = tid; f < 64 * 16; f += 256) {
        int r  = f >> 4;
        int kk = (f & 15) * 4;
        int row = row0 + r;
        float4 v = make_float4(0.f, 0.f, 0.f, 0.f);
        if (row < N) v = *(const float4*)(ev + (size_t)row * 64 + kk);
        *(float4*)(&ev_s[r * 64 + kk]) = v;
    }
    __syncthreads();

    {
        unsigned long long acc[16];
#pragma unroll
        for (int r = 0; r < 16; r++) acc[r] = 0ull;
        const float2* W2 = (const float2*)Wp;
        const float* xbase = &ev_s[grp * 16 * 64];
        for (int k = 0; k < 64; k += 4) {
            float2 w0 = W2[(k + 0) * 64 + c];
            float2 w1 = W2[(k + 1) * 64 + c];
            float2 w2 = W2[(k + 2) * 64 + c];
            float2 w3 = W2[(k + 3) * 64 + c];
            unsigned long long pw0 = pk2(w0.x, w0.y);
            unsigned long long pw1 = pk2(w1.x, w1.y);
            unsigned long long pw2 = pk2(w2.x, w2.y);
            unsigned long long pw3 = pk2(w3.x, w3.y);
#pragma unroll
            for (int r = 0; r < 16; r++) {
                float4 xv = *(const float4*)(xbase + r * 64 + k);
                acc[r] = ffma2(bc2(xv.x), pw0, acc[r]);
                acc[r] = ffma2(bc2(xv.y), pw1, acc[r]);
                acc[r] = ffma2(bc2(xv.z), pw2, acc[r]);
                acc[r] = ffma2(bc2(xv.w), pw3, acc[r]);
            }
        }
        float2 bb = ((const float2*)bp)[c];
#pragma unroll
        for (int r = 0; r < 16; r++) {
            float vx, vy;
            up2(acc[r], vx, vy);
            vx = fmaxf(vx + bb.x, 0.f);
            vy = fmaxf(vy + bb.y, 0.f);
            ((float2*)(&e1_s[(grp * 16 + r) * HID]))[c] = make_float2(vx, vy);
        }
    }
    __syncthreads();

    {
        unsigned long long acc[16];
#pragma unroll
        for (int r = 0; r < 16; r++) acc[r] = 0ull;
        const float2* W2 = (const float2*)Wg;
        const float* xbase = &e1_s[grp * 16 * HID];
        for (int k = 0; k < 128; k += 4) {
            float2 w0 = W2[(k + 0) * 64 + c];
            float2 w1 = W2[(k + 1) * 64 + c];
            float2 w2 = W2[(k + 2) * 64 + c];
            float2 w3 = W2[(k + 3) * 64 + c];
            unsigned long long pw0 = pk2(w0.x, w0.y);
            unsigned long long pw1 = pk2(w1.x, w1.y);
            unsigned long long pw2 = pk2(w2.x, w2.y);
            unsigned long long pw3 = pk2(w3.x, w3.y);
#pragma unroll
            for (int r = 0; r < 16; r++) {
                float4 xv = *(const float4*)(xbase + r * HID + k);
                acc[r] = ffma2(bc2(xv.x), pw0, acc[r]);
                acc[r] = ffma2(bc2(xv.y), pw1, acc[r]);
                acc[r] = ffma2(bc2(xv.z), pw2, acc[r]);
                acc[r] = ffma2(bc2(xv.w), pw3, acc[r]);
            }
        }
#pragma unroll
        for (int r = 0; r < 16; r++) {
            int row = row0 + grp * 16 + r;
            if (row >= N) break;
            float vx, vy;
            up2(acc[r], vx, vy);
            ((float2*)(&g_X[(size_t)row * HID]))[c] = make_float2(vx, vy);
        }
    }
}

// ---------------- CSR build ----------------
__global__ void zero_cnt(int N) {
    int i = blockIdx.x * blockDim.x + threadIdx.x;
    if (i < N) g_cnt[i] = 0;
}
__global__ void hist(const int* __restrict__ dst, int E, int N) {
    for (int e = blockIdx.x * blockDim.x + threadIdx.x; e < E;
         e += gridDim.x * blockDim.x) {
        unsigned d = (unsigned)dst[e];
        if (d < (unsigned)N) atomicAdd(&g_cnt[d], 1);
    }
}
__global__ void scan1(int N) {
    __shared__ int sm1[1024];
    int i = blockIdx.x * 1024 + threadIdx.x;
    int v = (i < N) ? g_cnt[i] : 0;
    sm1[threadIdx.x] = v;
    __syncthreads();
#pragma unroll
    for (int ofs = 1; ofs < 1024; ofs <<= 1) {
        int t = (threadIdx.x >= ofs) ? sm1[threadIdx.x - ofs] : 0;
        __syncthreads();
        sm1[threadIdx.x] += t;
        __syncthreads();
    }
    if (i < N) g_off[i] = sm1[threadIdx.x] - v;
    if (threadIdx.x == 1023) g_bsum[blockIdx.x] = sm1[1023];
}
__global__ void scan2(int nb) {
    __shared__ int sm2[128];
    int v = (threadIdx.x < nb) ? g_bsum[threadIdx.x] : 0;
    sm2[threadIdx.x] = v;
    __syncthreads();
#pragma unroll
    for (int ofs = 1; ofs < 128; ofs <<= 1) {
        int t = (threadIdx.x >= ofs) ? sm2[threadIdx.x - ofs] : 0;
        __syncthreads();
        sm2[threadIdx.x] += t;
        __syncthreads();
    }
    if (threadIdx.x < nb) g_bsum_ex[threadIdx.x] = sm2[threadIdx.x] - v;
}
__global__ void scan3(int N) {
    int i = blockIdx.x * 1024 + threadIdx.x;
    if (i >= N) return;
    int o = g_off[i] + g_bsum_ex[blockIdx.x];
    g_off[i] = o;
    g_cur[i] = o;
    g_dis[i] = rsqrtf((float)(g_cnt[i] + 1));
}
__global__ void fill_csr(const int* __restrict__ src,
                         const int* __restrict__ dst, int E, int N) {
    for (int e = blockIdx.x * blockDim.x + threadIdx.x; e < E;
         e += gridDim.x * blockDim.x) {
        unsigned d = (unsigned)dst[e];
        unsigned s = (unsigned)src[e];
        if (d < (unsigned)N && s < (unsigned)N) {
            int pos = atomicAdd(&g_cur[d], 1);
            if (pos < MAXE) g_esrc[pos] = (int)s;
        }
    }
}

// ---------------- aggregation ----------------
__global__ void __launch_bounds__(256) aggregate(int N) {
    int warp = (blockIdx.x * blockDim.x + threadIdx.x) >> 5;
    int lane = threadIdx.x & 31;
    if (warp >= N) return;
    int node = warp;
    float dd = g_dis[node];
    float inv = dd * dd;

    float4 acc = *(const float4*)(&g_X[(size_t)node * HID + lane * 4]);
    acc.x *= inv; acc.y *= inv; acc.z *= inv; acc.w *= inv;

    int beg = g_off[node];
    int end = beg + g_cnt[node];
    int i = beg;
    for (; i + 2 <= end; i += 2) {
        int s0 = g_esrc[i];
        int s1 = g_esrc[i + 1];
        float n0 = g_dis[s0] * dd;
        float n1 = g_dis[s1] * dd;
        float4 v0 = *(const float4*)(&g_X[(size_t)s0 * HID + lane * 4]);
        float4 v1 = *(const float4*)(&g_X[(size_t)s1 * HID + lane * 4]);
        acc.x = fmaf(v0.x, n0, acc.x);
        acc.y = fmaf(v0.y, n0, acc.y);
        acc.z = fmaf(v0.z, n0, acc.z);
        acc.w = fmaf(v0.w, n0, acc.w);
        acc.x = fmaf(v1.x, n1, acc.x);
        acc.y = fmaf(v1.y, n1, acc.y);
        acc.z = fmaf(v1.z, n1, acc.z);
        acc.w = fmaf(v1.w, n1, acc.w);
    }
    if (i < end) {
        int s = g_esrc[i];
        float nrm = g_dis[s] * dd;
        float4 v = *(const float4*)(&g_X[(size_t)s * HID + lane * 4]);
        acc.x = fmaf(v.x, nrm, acc.x);
        acc.y = fmaf(v.y, nrm, acc.y);
        acc.z = fmaf(v.z, nrm, acc.z);
        acc.w = fmaf(v.w, nrm, acc.w);
    }
    *(float4*)(&g_AGG[(size_t)node * HID + lane * 4]) = acc;
}

// ---------------- launch ----------------
extern "C" void kernel_launch(void* const* d_in, const int* in_sizes, int n_in,
                              void* d_out, int out_size) {
    const float* base = (const float*)d_in[0];
    const float* ev   = (const float*)d_in[1];
    const int*   ei   = (const int*)d_in[2];
    const float* Wp = (const float*)d_in[3];
    const float* bp = (const float*)d_in[4];
    const float* Wg = (const float*)d_in[5];
    const float* bg = (const float*)d_in[6];
    const float* Wga = (const float*)d_in[7];
    const float* bga = (const float*)d_in[8];
    const float* Wf = (const float*)d_in[9];
    const float* bf = (const float*)d_in[10];
    float* out = (float*)d_out;

    const int N = in_sizes[0] / HID;
    const int E = in_sizes[2] / 2;
    const int* src = ei;
    const int* dst = ei + E;
    const int nb = (N + 1023) / 1024;

    cudaFuncSetAttribute(gate_fuse_mma, cudaFuncAttributeMaxDynamicSharedMemorySize,
                         SMEM_BYTES);

    prep_w<<<128, 256>>>(Wga, Wf);
    proj_gcn_kernel<<<(N + 63) / 64, 256>>>(ev, Wp, bp, Wg, N);
    zero_cnt<<<(N + 255) / 256, 256>>>(N);
    hist<<<2368, 256>>>(dst, E, N);
    scan1<<<nb, 1024>>>(N);
    scan2<<<1, 128>>>(nb);
    scan3<<<nb, 1024>>>(N);
    fill_csr<<<2368, 256>>>(src, dst, E, N);
    aggregate<<<(N * 32 + 255) / 256, 256>>>(N);
    gate_fuse_mma<<<(N + 127) / 128, 256, SMEM_BYTES>>>(base, bga, bg, bf, out, N);
}